// round 13
// baseline (speedup 1.0000x reference)
#include <cuda_runtime.h>

#define SQ   1024   // spatial sequence length (16*64)
#define CH   64     // channels == heads (c = 1 per head)
#define NHB  128    // batch * heads
#define M    16     // Chebyshev terms
#define RAD  8.0f   // fixed Chebyshev interval [-RAD, RAD] for q
#define KS   0.18033688011112042f   // log2(e) / sqrt(64)
#define PI_M 0.19634954084936207f   // pi / 16

// ONLY inter-kernel state: 32 Chebyshev coefficients per head (16KB).
__device__ float g_coef[NHB * 32];

typedef unsigned long long u64t;

__device__ __forceinline__ float ex2f(float x) {
    float r;
    asm("ex2.approx.ftz.f32 %0, %1;" : "=f"(r) : "f"(x));
    return r;
}
__device__ __forceinline__ u64t pack2(float lo, float hi) {
    u64t r;
    asm("mov.b64 %0, {%1, %2};" : "=l"(r) : "f"(lo), "f"(hi));
    return r;
}
__device__ __forceinline__ float2 unpack2(u64t v) {
    float2 f;
    asm("mov.b64 {%0, %1}, %2;" : "=f"(f.x), "=f"(f.y) : "l"(v));
    return f;
}
__device__ __forceinline__ u64t fma2(u64t a, u64t b, u64t c) {
    u64t d;
    asm("fma.rn.f32x2 %0, %1, %2, %3;" : "=l"(d) : "l"(a), "l"(b), "l"(c));
    return d;
}
__device__ __forceinline__ u64t add2(u64t a, u64t b) {
    u64t d;
    asm("add.rn.f32x2 %0, %1, %2;" : "=l"(d) : "l"(a), "l"(b));
    return d;
}

// ---------------------------------------------------------------------------
// K1: per-head-pair Chebyshev coefficients, straight from x.
// Block = (b, head pair) -> 64 blocks, 256 threads.
//   Phase 1: k-hat, v rows for heads 2g, 2g+1 (dot-GEMV; 64 independent
//            LDG.128 per thread, x[b] shared by 32 blocks -> L2-resident).
//            k-hat/v live ONLY in smem.
//   Phase 2: 16-node exp sums per head (warp-strided), warp reductions.
//   Phase 3: DCT -> 32 coefficients per head -> g_coef.
// ---------------------------------------------------------------------------
__global__ __launch_bounds__(256) void coef_kernel(
    const float* __restrict__ x,
    const float* __restrict__ Wk, const float* __restrict__ bk,
    const float* __restrict__ Wv, const float* __restrict__ bv)
{
    __shared__ __align__(16) float wsh[4][CH];   // kA, kB (pre-scaled), vA, vB
    __shared__ __align__(16) float kh[2][SQ];
    __shared__ __align__(16) float vv[2][SQ];
    __shared__ float fj[2][M], gj[2][M];

    const int tid = threadIdx.x;
    const int b   = blockIdx.x >> 5;
    const int g   = blockIdx.x & 31;
    const int hA  = 2 * g, hB = 2 * g + 1;

    {
        const int r = tid >> 6, c = tid & 63;
        if (r == 0)      wsh[0][c] = Wk[hA * CH + c] * KS;
        else if (r == 1) wsh[1][c] = Wk[hB * CH + c] * KS;
        else if (r == 2) wsh[2][c] = Wv[hA * CH + c];
        else             wsh[3][c] = Wv[hB * CH + c];
    }
    __syncthreads();

    // Phase 1: each thread computes 4 consecutive t for both heads.
    const int t0 = tid * 4;
    const float bkA = bk[hA] * KS, bkB = bk[hB] * KS;
    const float bvA = bv[hA],      bvB = bv[hB];
    u64t kA01 = pack2(bkA, bkA), kA23 = kA01;
    u64t kB01 = pack2(bkB, bkB), kB23 = kB01;
    u64t vA01 = pack2(bvA, bvA), vA23 = vA01;
    u64t vB01 = pack2(bvB, bvB), vB23 = vB01;

    const float* xb = x + (size_t)b * CH * SQ + t0;
#pragma unroll
    for (int c = 0; c < CH; c++) {
        float4 xv = *reinterpret_cast<const float4*>(xb + c * SQ);
        u64t x01 = pack2(xv.x, xv.y), x23 = pack2(xv.z, xv.w);
        float w; u64t w2;
        w = wsh[0][c]; w2 = pack2(w, w);
        kA01 = fma2(w2, x01, kA01); kA23 = fma2(w2, x23, kA23);
        w = wsh[1][c]; w2 = pack2(w, w);
        kB01 = fma2(w2, x01, kB01); kB23 = fma2(w2, x23, kB23);
        w = wsh[2][c]; w2 = pack2(w, w);
        vA01 = fma2(w2, x01, vA01); vA23 = fma2(w2, x23, vA23);
        w = wsh[3][c]; w2 = pack2(w, w);
        vB01 = fma2(w2, x01, vB01); vB23 = fma2(w2, x23, vB23);
    }
    {
        // 8-byte stores on 8-byte-aligned addresses (t0*4 is 16B-multiple,
        // bases are __align__(16)) — alignment-safe.
        u64t* p;
        p = reinterpret_cast<u64t*>(&kh[0][t0]); p[0] = kA01; p[1] = kA23;
        p = reinterpret_cast<u64t*>(&kh[1][t0]); p[0] = kB01; p[1] = kB23;
        p = reinterpret_cast<u64t*>(&vv[0][t0]); p[0] = vA01; p[1] = vA23;
        p = reinterpret_cast<u64t*>(&vv[1][t0]); p[0] = vB01; p[1] = vB23;
    }
    __syncthreads();

    // Phase 2: 32 (head, node) items over 8 warps -> 4 items per warp.
    const int w = tid >> 5, l = tid & 31;
#pragma unroll
    for (int it = w; it < 32; it += 8) {
        const int hh = it >> 4, n = it & 15;
        const float xn = RAD * cosf(((float)n + 0.5f) * PI_M);
        float f0 = 0.f, g0 = 0.f;
#pragma unroll 8
        for (int t = l; t < SQ; t += 32) {
            float e = ex2f(xn * kh[hh][t]);
            f0 += e;
            g0 = fmaf(e, vv[hh][t], g0);
        }
#pragma unroll
        for (int d = 16; d; d >>= 1) {
            f0 += __shfl_xor_sync(0xffffffffu, f0, d);
            g0 += __shfl_xor_sync(0xffffffffu, g0, d);
        }
        if (l == 0) { fj[hh][n] = f0; gj[hh][n] = g0; }
    }
    __syncthreads();

    // Phase 3: DCT -> coefficients (threads 0..31: 2 heads x 16 k)
    if (tid < 32) {
        const int hh = tid >> 4, k = tid & 15;
        float af = 0.f, ag = 0.f;
#pragma unroll
        for (int j = 0; j < M; j++) {
            float wgt = cosf((float)k * ((float)j + 0.5f) * PI_M);
            af = fmaf(fj[hh][j], wgt, af);
            ag = fmaf(gj[hh][j], wgt, ag);
        }
        const float sc = (k == 0) ? (1.0f / M) : (2.0f / M);
        const int head = b * CH + 2 * g + hh;
        g_coef[head * 32 + k]      = af * sc;
        g_coef[head * 32 + 16 + k] = ag * sc;
    }
}

// ---------------------------------------------------------------------------
// K2: q projection + Clenshaw + Wo GEMM + residual, all in one block.
// Block = (16-s tile, b) -> 128 blocks, 256 threads.
// Thread (o = tid>>2, sq = tid&3) handles head/out-channel o, 4 s values.
// Tile rows padded to 20 floats (80B, 16B-divisible) for aligned float4.
// ---------------------------------------------------------------------------
__global__ __launch_bounds__(256) void qout_kernel(
    const float* __restrict__ x,
    const float* __restrict__ Wq, const float* __restrict__ bq,
    const float* __restrict__ Wo, const float* __restrict__ bo,
    float* __restrict__ outp)
{
    __shared__ __align__(16) float wq[CH][68];   // 272B rows (16B-divisible)
    __shared__ __align__(16) float wo[CH][68];
    __shared__ __align__(16) float xt[CH][20];   // 80B rows (16B-divisible)
    __shared__ __align__(16) float ot[CH][20];
    __shared__ float ca[CH][17], cb[CH][17];

    const int tid = threadIdx.x;
    const int b   = blockIdx.y;
    const int s0  = blockIdx.x * 16;

    // Upfront coalesced staging (all LDGs independent -> one L2 round trip).
#pragma unroll
    for (int i = tid * 4; i < CH * CH; i += 1024) {
        float4 a  = *reinterpret_cast<const float4*>(Wq + i);
        float4 bw = *reinterpret_cast<const float4*>(Wo + i);
        *reinterpret_cast<float4*>(&wq[i >> 6][i & 63]) = a;
        *reinterpret_cast<float4*>(&wo[i >> 6][i & 63]) = bw;
    }
#pragma unroll
    for (int i = tid * 4; i < CH * 32; i += 1024) {
        float4 cv = *reinterpret_cast<const float4*>(g_coef + b * CH * 32 + i);
#pragma unroll
        for (int u = 0; u < 4; u++) {
            const int idx = i + u, h = idx >> 5, r = idx & 31;
            const float val = (&cv.x)[u];
            if (r < 16) ca[h][r] = val; else cb[h][r - 16] = val;
        }
    }
    {
        const int c = tid >> 2, j = tid & 3;
        float4 xv = *reinterpret_cast<const float4*>(
            x + (size_t)(b * CH + c) * SQ + s0 + 4 * j);
        *reinterpret_cast<float4*>(&xt[c][4 * j]) = xv;
    }
    __syncthreads();

    const int o = tid >> 2, sq = tid & 3;

    // q GEMV: 4 independent accumulator chains (2 s-pairs x even/odd halves)
    u64t qa01 = pack2(bq[o], bq[o]), qa23 = qa01;
    u64t qb01 = pack2(0.f, 0.f),     qb23 = qb01;
#pragma unroll
    for (int c4 = 0; c4 < CH / 8; c4++) {
        float4 wA = *reinterpret_cast<const float4*>(&wq[o][c4 * 8]);
        float4 wB = *reinterpret_cast<const float4*>(&wq[o][c4 * 8 + 4]);
#pragma unroll
        for (int u = 0; u < 4; u++) {
            const u64t* xpA = reinterpret_cast<const u64t*>(&xt[c4 * 8 + u][4 * sq]);
            u64t w2 = pack2((&wA.x)[u], (&wA.x)[u]);
            qa01 = fma2(w2, xpA[0], qa01);
            qa23 = fma2(w2, xpA[1], qa23);
            const u64t* xpB = reinterpret_cast<const u64t*>(&xt[c4 * 8 + 4 + u][4 * sq]);
            u64t w2b = pack2((&wB.x)[u], (&wB.x)[u]);
            qb01 = fma2(w2b, xpB[0], qb01);
            qb23 = fma2(w2b, xpB[1], qb23);
        }
    }
    float2 q01 = unpack2(add2(qa01, qb01));
    float2 q23 = unpack2(add2(qa23, qb23));

    // Clenshaw on the 4 q values (fixed interval: u = q / RAD)
    {
        const float IR = 1.0f / RAD;
        float u0 = q01.x * IR, u1 = q01.y * IR, u2 = q23.x * IR, u3 = q23.y * IR;
        float t0 = 2.f * u0, t1 = 2.f * u1, t2 = 2.f * u2, t3 = 2.f * u3;
        float b10 = 0.f, b20 = 0.f, d10 = 0.f, d20 = 0.f;
        float b11 = 0.f, b21 = 0.f, d11 = 0.f, d21 = 0.f;
        float b12 = 0.f, b22 = 0.f, d12 = 0.f, d22 = 0.f;
        float b13 = 0.f, b23 = 0.f, d13 = 0.f, d23 = 0.f;
#pragma unroll
        for (int k = M - 1; k >= 1; k--) {
            float cak = ca[o][k], cbk = cb[o][k];
            float nb0 = fmaf(t0, b10, cak - b20); b20 = b10; b10 = nb0;
            float nd0 = fmaf(t0, d10, cbk - d20); d20 = d10; d10 = nd0;
            float nb1 = fmaf(t1, b11, cak - b21); b21 = b11; b11 = nb1;
            float nd1 = fmaf(t1, d11, cbk - d21); d21 = d11; d11 = nd1;
            float nb2 = fmaf(t2, b12, cak - b22); b22 = b12; b12 = nb2;
            float nd2 = fmaf(t2, d12, cbk - d22); d22 = d12; d12 = nd2;
            float nb3 = fmaf(t3, b13, cak - b23); b23 = b13; b13 = nb3;
            float nd3 = fmaf(t3, d13, cbk - d23); d23 = d13; d13 = nd3;
        }
        float ca0 = ca[o][0], cb0 = cb[o][0];
        float4 r4;
        r4.x = __fdividef(fmaf(u0, d10, cb0 - d20), fmaf(u0, b10, ca0 - b20));
        r4.y = __fdividef(fmaf(u1, d11, cb0 - d21), fmaf(u1, b11, ca0 - b21));
        r4.z = __fdividef(fmaf(u2, d12, cb0 - d22), fmaf(u2, b12, ca0 - b22));
        r4.w = __fdividef(fmaf(u3, d13, cb0 - d23), fmaf(u3, b13, ca0 - b23));
        *reinterpret_cast<float4*>(&ot[o][4 * sq]) = r4;   // own slot: safe
    }
    __syncthreads();

    // Wo GEMM (4 chains) + residual
    u64t a01 = pack2(bo[o], bo[o]), a23 = a01;
    u64t c01 = pack2(0.f, 0.f),     c23 = c01;
#pragma unroll
    for (int c4 = 0; c4 < CH / 8; c4++) {
        float4 wA = *reinterpret_cast<const float4*>(&wo[o][c4 * 8]);
        float4 wB = *reinterpret_cast<const float4*>(&wo[o][c4 * 8 + 4]);
#pragma unroll
        for (int u = 0; u < 4; u++) {
            const u64t* opA = reinterpret_cast<const u64t*>(&ot[c4 * 8 + u][4 * sq]);
            u64t w2 = pack2((&wA.x)[u], (&wA.x)[u]);
            a01 = fma2(w2, opA[0], a01);
            a23 = fma2(w2, opA[1], a23);
            const u64t* opB = reinterpret_cast<const u64t*>(&ot[c4 * 8 + 4 + u][4 * sq]);
            u64t w2b = pack2((&wB.x)[u], (&wB.x)[u]);
            c01 = fma2(w2b, opB[0], c01);
            c23 = fma2(w2b, opB[1], c23);
        }
    }
    const size_t idx = (size_t)(b * CH + o) * SQ + s0 + 4 * sq;
    float4 rv = *reinterpret_cast<const float4*>(x + idx);
    float2 s01 = unpack2(add2(a01, c01));
    float2 s23 = unpack2(add2(a23, c23));
    float4 o4;
    o4.x = s01.x + rv.x; o4.y = s01.y + rv.y;
    o4.z = s23.x + rv.z; o4.w = s23.y + rv.w;
    *reinterpret_cast<float4*>(outp + idx) = o4;
}

extern "C" void kernel_launch(void* const* d_in, const int* in_sizes, int n_in,
                              void* d_out, int out_size)
{
    const float* x  = (const float*)d_in[0];
    const float* Wq = (const float*)d_in[1];
    const float* bq = (const float*)d_in[2];
    const float* Wk = (const float*)d_in[3];
    const float* bk = (const float*)d_in[4];
    const float* Wv = (const float*)d_in[5];
    const float* bv = (const float*)d_in[6];
    const float* Wo = (const float*)d_in[7];
    const float* bo = (const float*)d_in[8];
    float* out = (float*)d_out;

    coef_kernel<<<64, 256>>>(x, Wk, bk, Wv, bv);

    dim3 grid(SQ / 16, 2);
    qout_kernel<<<grid, 256>>>(x, Wq, bq, Wo, bo, out);
}